// round 1
// baseline (speedup 1.0000x reference)
#include <cuda_runtime.h>
#include <math.h>

// Problem constants
#define BB   64
#define TT   512
#define DD   256
#define HH   512
#define NCTA 128
#define NTH  256

// ---------------------------------------------------------------------------
// Global scratch (static __device__ arrays: no allocations allowed)
// ---------------------------------------------------------------------------
__device__ float g_xT[TT * DD * BB];      // x transposed: [t][d][b]   (32 MB)
__device__ float g_out0[TT * HH * BB];    // layer0 output: [t][h][b]  (64 MB)
__device__ float g_hbuf[2 * HH * BB];     // double-buffered h: [buf][h][b]
__device__ unsigned g_bar_count;          // grid barrier arrival counter
__device__ unsigned g_bar_epoch;          // grid barrier epoch (monotonic across replays)

// ---------------------------------------------------------------------------
// Grid barrier: all 128 CTAs are guaranteed co-resident (128 < 148 SMs,
// 1 CTA/SM by smem). Epoch-based, self-resetting counter (count returns to 0
// at the end of every launch, epoch is monotonic -> graph-replay safe).
// ---------------------------------------------------------------------------
__device__ __forceinline__ void grid_barrier(int tid, unsigned& target) {
    __threadfence();
    __syncthreads();
    target += 1;
    if (tid == 0) {
        unsigned old = atomicAdd(&g_bar_count, 1u);
        if (old == NCTA - 1) {
            atomicExch(&g_bar_count, 0u);
            __threadfence();
            atomicAdd(&g_bar_epoch, 1u);
        } else {
            while ((int)(*(volatile unsigned*)&g_bar_epoch - target) < 0) {
                __nanosleep(64);
            }
            __threadfence();
        }
    }
    __syncthreads();
}

// ---------------------------------------------------------------------------
// Transpose x: [b][t][d] -> xT [t][d][b]
// ---------------------------------------------------------------------------
__global__ void transpose_x_kernel(const float* __restrict__ x) {
    extern __shared__ float sm[];  // [256][65]
    const int t = blockIdx.x;
    const int tid = threadIdx.x;
    for (int i = tid; i < BB * DD; i += NTH) {
        int b = i >> 8;          // /256
        int d = i & 255;
        sm[d * 65 + b] = x[(size_t)b * (TT * DD) + (size_t)t * DD + d];
    }
    __syncthreads();
    float* dst = g_xT + (size_t)t * (DD * BB);
    for (int i = tid; i < DD * BB; i += NTH) {
        int d = i >> 6;          // /64
        int b = i & 63;
        dst[i] = sm[d * 65 + b];
    }
}

// ---------------------------------------------------------------------------
// Persistent LSTM layer kernel.
//   KX    = input feature dim for this layer (256 or 512)
//   LAYER = 0 or 1
// 128 CTAs; CTA c owns hidden units [4c, 4c+4)  (16 gate rows: r = gate*4+ul).
// Thread layout: rg = tid&3 (row group of 4), bg = (tid>>2)&7 (batch group of
// 8), ws = tid>>5 (K slice, = warp id). Each warp owns a contiguous 16-k slice
// of every 128-k chunk; per k it does 3 conflict-free LDS.128 + 32 FFMA.
// ---------------------------------------------------------------------------
template <int KX, int LAYER>
__global__ void lstm_layer_kernel(const float* __restrict__ W_ih,
                                  const float* __restrict__ W_hh,
                                  const float* __restrict__ b_ih,
                                  const float* __restrict__ b_hh,
                                  float* __restrict__ d_out) {
    constexpr int KTOT = KX + HH;
    extern __shared__ float smem[];
    float* W_s   = smem;                   // [KTOT][16]  k-major
    float* stage = W_s + KTOT * 16;        // [128][64]   current chunk (x or h)
    float* part  = stage + 128 * 64;       // [8][16][64] K-slice partials
    float* gates = part + 8 * 16 * 64;     // [16][64]    gate pre-activations
    float* c_s   = gates + 16 * 64;        // [4][64]     cell state slice
    float* bias_s = c_s + 4 * 64;          // [16]

    const int tid = threadIdx.x;
    const int cta = blockIdx.x;
    const int rg = tid & 3;
    const int bg = (tid >> 2) & 7;
    const int ws = tid >> 5;

    // --- stage weights once (persist whole kernel) ---
    for (int i = tid; i < 16 * KTOT; i += NTH) {
        int r = i / KTOT;
        int k = i - r * KTOT;
        int j = (r >> 2) * HH + cta * 4 + (r & 3);
        float v = (k < KX) ? W_ih[(size_t)j * KX + k]
                           : W_hh[(size_t)j * HH + (k - KX)];
        W_s[k * 16 + r] = v;
    }
    if (tid < 16) {
        int j = (tid >> 2) * HH + cta * 4 + (tid & 3);
        bias_s[tid] = b_ih[j] + b_hh[j];
    }
    c_s[tid] = 0.0f;  // 4*64 == 256 == NTH
    {   // zero hbuf[0] for our columns
        int ul = tid >> 6, b = tid & 63;
        g_hbuf[(cta * 4 + ul) * BB + b] = 0.0f;
    }

    unsigned bar_target = 0;
    if (tid == 0) bar_target = *(volatile unsigned*)&g_bar_epoch;
    grid_barrier(tid, bar_target);   // hbuf zeros visible everywhere

    const float* xbase = (LAYER == 0) ? g_xT : g_out0;

    for (int t = 0; t < TT; ++t) {
        float acc[4][8];
        #pragma unroll
        for (int ri = 0; ri < 4; ++ri)
            #pragma unroll
            for (int bi = 0; bi < 8; ++bi) acc[ri][bi] = 0.0f;

        #pragma unroll
        for (int sg = 0; sg < 2; ++sg) {
            const float* src;
            int nch, wofs;
            if (sg == 0) { src = xbase + (size_t)t * (KX * BB); nch = KX / 128; wofs = 0; }
            else         { src = g_hbuf + (t & 1) * (HH * BB);  nch = HH / 128; wofs = KX; }

            for (int c = 0; c < nch; ++c) {
                __syncthreads();  // previous chunk fully consumed
                const float4* g4 = reinterpret_cast<const float4*>(src) + c * 2048;
                float4* s4 = reinterpret_cast<float4*>(stage);
                #pragma unroll
                for (int i = 0; i < 8; ++i)
                    s4[tid + i * NTH] = __ldcg(g4 + tid + i * NTH);
                __syncthreads();

                const float* wb = W_s + (wofs + c * 128) * 16;
                #pragma unroll
                for (int kk = 0; kk < 16; ++kk) {
                    const int kl = (ws << 4) | kk;
                    const float4 w4 = *reinterpret_cast<const float4*>(wb + kl * 16 + (rg << 2));
                    const float4 a0 = *reinterpret_cast<const float4*>(stage + (kl << 6) + (bg << 3));
                    const float4 a1 = *reinterpret_cast<const float4*>(stage + (kl << 6) + (bg << 3) + 4);
                    const float wv[4] = {w4.x, w4.y, w4.z, w4.w};
                    const float av[8] = {a0.x, a0.y, a0.z, a0.w, a1.x, a1.y, a1.z, a1.w};
                    #pragma unroll
                    for (int ri = 0; ri < 4; ++ri)
                        #pragma unroll
                        for (int bi = 0; bi < 8; ++bi)
                            acc[ri][bi] = fmaf(wv[ri], av[bi], acc[ri][bi]);
                }
            }
        }

        // --- reduce 8 K-slice partials via smem ---
        __syncthreads();
        {
            const int bb = bg << 3;
            #pragma unroll
            for (int ri = 0; ri < 4; ++ri) {
                float* p = part + ws * 1024 + ((rg << 2) + ri) * 64 + bb;
                *reinterpret_cast<float4*>(p)     = make_float4(acc[ri][0], acc[ri][1], acc[ri][2], acc[ri][3]);
                *reinterpret_cast<float4*>(p + 4) = make_float4(acc[ri][4], acc[ri][5], acc[ri][6], acc[ri][7]);
            }
        }
        __syncthreads();
        {
            const int row = tid >> 4;
            const int b0 = (tid & 15) << 2;
            float4 s = make_float4(0.f, 0.f, 0.f, 0.f);
            #pragma unroll
            for (int p = 0; p < 8; ++p) {
                const float4 v = *reinterpret_cast<const float4*>(part + p * 1024 + row * 64 + b0);
                s.x += v.x; s.y += v.y; s.z += v.z; s.w += v.w;
            }
            const float bias = bias_s[row];
            *reinterpret_cast<float4*>(gates + row * 64 + b0) =
                make_float4(s.x + bias, s.y + bias, s.z + bias, s.w + bias);
        }
        __syncthreads();

        // --- cell update: one thread per (unit, batch) ---
        {
            const int ul = tid >> 6;
            const int b = tid & 63;
            const float gi = gates[(0 * 4 + ul) * 64 + b];
            const float gf = gates[(1 * 4 + ul) * 64 + b];
            const float gg = gates[(2 * 4 + ul) * 64 + b];
            const float go = gates[(3 * 4 + ul) * 64 + b];
            const float i_ = 1.0f / (1.0f + expf(-gi));
            const float f_ = 1.0f / (1.0f + expf(-gf));
            const float g_ = tanhf(gg);
            const float o_ = 1.0f / (1.0f + expf(-go));
            const float cn = f_ * c_s[ul * 64 + b] + i_ * g_;
            c_s[ul * 64 + b] = cn;
            const float h = o_ * tanhf(cn);
            const int col = cta * 4 + ul;
            g_hbuf[((t + 1) & 1) * (HH * BB) + col * BB + b] = h;
            if (LAYER == 0)
                g_out0[(size_t)t * (HH * BB) + col * BB + b] = h;
            if (t == TT - 1) {
                d_out[64 + LAYER * (BB * HH) + (size_t)b * HH + col] = h;                  // hn
                d_out[64 + 2 * (BB * HH) + LAYER * (BB * HH) + (size_t)b * HH + col] = cn; // cn
            }
        }
        grid_barrier(tid, bar_target);
    }
}

// ---------------------------------------------------------------------------
// FC: out[b] = dot(hn1[b,:], fc_w) + fc_b   (hn1 lives in d_out already)
// ---------------------------------------------------------------------------
__global__ void fc_kernel(const float* __restrict__ fc_w,
                          const float* __restrict__ fc_b,
                          float* __restrict__ d_out) {
    const int b = blockIdx.x;
    const int tid = threadIdx.x;
    const float* h = d_out + 64 + (BB * HH) + (size_t)b * HH;  // hn layer 1
    float s = 0.0f;
    for (int k = tid; k < HH; k += 128) s += h[k] * fc_w[k];
    #pragma unroll
    for (int off = 16; off > 0; off >>= 1) s += __shfl_down_sync(0xffffffffu, s, off);
    __shared__ float wsum[4];
    if ((tid & 31) == 0) wsum[tid >> 5] = s;
    __syncthreads();
    if (tid == 0) d_out[b] = wsum[0] + wsum[1] + wsum[2] + wsum[3] + fc_b[0];
}

// ---------------------------------------------------------------------------
// Launch
// inputs: x, W_ih0, W_hh0, b_ih0, b_hh0, W_ih1, W_hh1, b_ih1, b_hh1, fc_w, fc_b
// output: [out(64) | hn(2*64*512) | cn(2*64*512)] float32
// ---------------------------------------------------------------------------
extern "C" void kernel_launch(void* const* d_in, const int* in_sizes, int n_in,
                              void* d_out, int out_size) {
    const float* x     = (const float*)d_in[0];
    const float* W_ih0 = (const float*)d_in[1];
    const float* W_hh0 = (const float*)d_in[2];
    const float* b_ih0 = (const float*)d_in[3];
    const float* b_hh0 = (const float*)d_in[4];
    const float* W_ih1 = (const float*)d_in[5];
    const float* W_hh1 = (const float*)d_in[6];
    const float* b_ih1 = (const float*)d_in[7];
    const float* b_hh1 = (const float*)d_in[8];
    const float* fc_w  = (const float*)d_in[9];
    const float* fc_b  = (const float*)d_in[10];
    float* out = (float*)d_out;

    const int smem_tr = 256 * 65 * 4;                                   // 66560
    const int smem_l0 = ((256 + HH) * 16 + 128 * 64 + 8 * 16 * 64 + 16 * 64 + 4 * 64 + 16) * 4;
    const int smem_l1 = ((512 + HH) * 16 + 128 * 64 + 8 * 16 * 64 + 16 * 64 + 4 * 64 + 16) * 4;

    cudaFuncSetAttribute(transpose_x_kernel,
                         cudaFuncAttributeMaxDynamicSharedMemorySize, smem_tr);
    cudaFuncSetAttribute(lstm_layer_kernel<256, 0>,
                         cudaFuncAttributeMaxDynamicSharedMemorySize, smem_l0);
    cudaFuncSetAttribute(lstm_layer_kernel<512, 1>,
                         cudaFuncAttributeMaxDynamicSharedMemorySize, smem_l1);

    transpose_x_kernel<<<TT, NTH, smem_tr>>>(x);
    lstm_layer_kernel<256, 0><<<NCTA, NTH, smem_l0>>>(W_ih0, W_hh0, b_ih0, b_hh0, out);
    lstm_layer_kernel<512, 1><<<NCTA, NTH, smem_l1>>>(W_ih1, W_hh1, b_ih1, b_hh1, out);
    fc_kernel<<<BB, 128>>>(fc_w, fc_b, out);
}

// round 2
// speedup vs baseline: 1.1817x; 1.1817x over previous
#include <cuda_runtime.h>
#include <math.h>

// Problem constants
#define BB   64
#define TT   512
#define DD   256
#define HH   512
#define NCTA 128
#define NTH  256

// ---------------------------------------------------------------------------
// Global scratch
// ---------------------------------------------------------------------------
__device__ float g_xT[TT * DD * BB];      // x transposed: [t][d][b]
__device__ float g_out0[TT * HH * BB];    // layer0 output: [t][h][b]
__device__ float g_hbuf[2 * HH * BB];     // double-buffered h: [buf][h][b]
__device__ unsigned g_bar_count;
__device__ unsigned g_bar_epoch;

// ---------------------------------------------------------------------------
// Packed f32x2 helpers (SASS FFMA2: 2 fp32 FMAs per instruction, fma pipe)
// ---------------------------------------------------------------------------
__device__ __forceinline__ void ffma2(unsigned long long& d,
                                      unsigned long long a,
                                      unsigned long long b) {
    asm("fma.rn.f32x2 %0, %1, %2, %0;" : "+l"(d) : "l"(a), "l"(b));
}
__device__ __forceinline__ void fadd2(unsigned long long& d, unsigned long long a) {
    asm("add.rn.f32x2 %0, %0, %1;" : "+l"(d) : "l"(a));
}
__device__ __forceinline__ unsigned long long pack_dup(float w) {
    unsigned long long r;
    asm("mov.b64 %0, {%1, %1};" : "=l"(r) : "f"(w));
    return r;
}

// ---------------------------------------------------------------------------
// Grid barrier: 128 CTAs, 1 CTA/SM (smem-limited) -> all co-resident.
// Epoch-based, self-resetting, graph-replay safe.
// ---------------------------------------------------------------------------
__device__ __forceinline__ void grid_barrier(int tid, unsigned& target) {
    __threadfence();
    __syncthreads();
    target += 1;
    if (tid == 0) {
        unsigned old = atomicAdd(&g_bar_count, 1u);
        if (old == NCTA - 1) {
            atomicExch(&g_bar_count, 0u);
            __threadfence();
            atomicAdd(&g_bar_epoch, 1u);
        } else {
            while ((int)(*(volatile unsigned*)&g_bar_epoch - target) < 0) {
                __nanosleep(64);
            }
            __threadfence();
        }
    }
    __syncthreads();
}

// ---------------------------------------------------------------------------
// Transpose x: [b][t][d] -> xT [t][d][b]
// ---------------------------------------------------------------------------
__global__ void transpose_x_kernel(const float* __restrict__ x) {
    extern __shared__ float sm[];  // [256][65]
    const int t = blockIdx.x;
    const int tid = threadIdx.x;
    for (int i = tid; i < BB * DD; i += NTH) {
        int b = i >> 8;
        int d = i & 255;
        sm[d * 65 + b] = x[(size_t)b * (TT * DD) + (size_t)t * DD + d];
    }
    __syncthreads();
    float* dst = g_xT + (size_t)t * (DD * BB);
    for (int i = tid; i < DD * BB; i += NTH) {
        int d = i >> 6;
        int b = i & 63;
        dst[i] = sm[d * 65 + b];
    }
}

// ---------------------------------------------------------------------------
// Persistent LSTM layer kernel (f32x2 + double-buffered staging pipeline).
// CTA c owns 4 hidden units (16 gate rows). Thread layout:
//   rg = tid&3 (row group of 4), bg = (tid>>2)&7 (batch group of 8, processed
//   as 4 packed pairs), ws = tid>>5 (warp-owned 16-k slice of each 128-k chunk)
// ---------------------------------------------------------------------------
template <int KX, int LAYER>
__global__ void lstm_layer_kernel(const float* __restrict__ W_ih,
                                  const float* __restrict__ W_hh,
                                  const float* __restrict__ b_ih,
                                  const float* __restrict__ b_hh,
                                  float* __restrict__ d_out) {
    constexpr int KTOT = KX + HH;
    constexpr int NCX  = KX / 128;        // x chunks
    constexpr int NCH  = NCX + HH / 128;  // total chunks per step
    extern __shared__ float smem[];
    float* W_s   = smem;                   // [KTOT][16]   k-major
    float* stage = W_s + KTOT * 16;        // [2][128][64] double-buffered chunk
    float* part  = stage + 2 * 128 * 64;   // [8][16][64]  K-slice partials
    float* gates = part + 8 * 16 * 64;     // [16][64]
    float* c_s   = gates + 16 * 64;        // [4][64]
    float* bias_s = c_s + 4 * 64;          // [16]

    const int tid = threadIdx.x;
    const int cta = blockIdx.x;
    const int rg = tid & 3;
    const int bg = (tid >> 2) & 7;
    const int ws = tid >> 5;

    // --- stage weights once ---
    for (int i = tid; i < 16 * KTOT; i += NTH) {
        int r = i / KTOT;
        int k = i - r * KTOT;
        int j = (r >> 2) * HH + cta * 4 + (r & 3);
        float v = (k < KX) ? W_ih[(size_t)j * KX + k]
                           : W_hh[(size_t)j * HH + (k - KX)];
        W_s[k * 16 + r] = v;
    }
    if (tid < 16) {
        int j = (tid >> 2) * HH + cta * 4 + (tid & 3);
        bias_s[tid] = b_ih[j] + b_hh[j];
    }
    c_s[tid] = 0.0f;
    {
        int ul = tid >> 6, b = tid & 63;
        g_hbuf[(cta * 4 + ul) * BB + b] = 0.0f;
    }

    unsigned bar_target = 0;
    if (tid == 0) bar_target = *(volatile unsigned*)&g_bar_epoch;
    grid_barrier(tid, bar_target);

    const float* xbase = (LAYER == 0) ? g_xT : g_out0;

    for (int t = 0; t < TT; ++t) {
        const float* xstep = xbase + (size_t)t * (KX * BB);
        const float* hstep = g_hbuf + (t & 1) * (HH * BB);

        // chunk source resolver (chunk = 8192 floats = 128k x 64b)
        auto chunk_src = [&](int c) -> const float4* {
            const float* s = (c < NCX) ? (xstep + (c << 13))
                                       : (hstep + ((c - NCX) << 13));
            return reinterpret_cast<const float4*>(s);
        };

        unsigned long long acc2[4][4];
        #pragma unroll
        for (int ri = 0; ri < 4; ++ri)
            #pragma unroll
            for (int bj = 0; bj < 4; ++bj) acc2[ri][bj] = 0ull;

        // --- prime pipeline: chunk 0 -> buf 0 ---
        float4 pf[8];
        {
            const float4* g4 = chunk_src(0);
            #pragma unroll
            for (int i = 0; i < 8; ++i) pf[i] = __ldcg(g4 + tid + i * NTH);
            float4* d4 = reinterpret_cast<float4*>(stage);
            #pragma unroll
            for (int i = 0; i < 8; ++i) d4[tid + i * NTH] = pf[i];
        }
        __syncthreads();

        for (int c = 0; c < NCH; ++c) {
            const int cur = c & 1;
            // issue prefetch of next chunk early (overlaps with compute)
            if (c + 1 < NCH) {
                const float4* g4 = chunk_src(c + 1);
                #pragma unroll
                for (int i = 0; i < 8; ++i) pf[i] = __ldcg(g4 + tid + i * NTH);
            }

            const float* sbuf = stage + cur * (128 * 64);
            const float* wb = W_s + (c * 128) * 16;
            #pragma unroll
            for (int kk = 0; kk < 16; ++kk) {
                const int kl = (ws << 4) | kk;
                const float4 w4 = *reinterpret_cast<const float4*>(wb + kl * 16 + (rg << 2));
                unsigned long long wd[4] = {pack_dup(w4.x), pack_dup(w4.y),
                                            pack_dup(w4.z), pack_dup(w4.w)};
                const ulonglong2 a0 = *reinterpret_cast<const ulonglong2*>(sbuf + (kl << 6) + (bg << 3));
                const ulonglong2 a1 = *reinterpret_cast<const ulonglong2*>(sbuf + (kl << 6) + (bg << 3) + 4);
                const unsigned long long av[4] = {a0.x, a0.y, a1.x, a1.y};
                #pragma unroll
                for (int ri = 0; ri < 4; ++ri)
                    #pragma unroll
                    for (int bj = 0; bj < 4; ++bj)
                        ffma2(acc2[ri][bj], wd[ri], av[bj]);
            }

            // drain prefetch into the other buffer
            if (c + 1 < NCH) {
                float4* d4 = reinterpret_cast<float4*>(stage + (cur ^ 1) * (128 * 64));
                #pragma unroll
                for (int i = 0; i < 8; ++i) d4[tid + i * NTH] = pf[i];
            }
            __syncthreads();
        }

        // --- write K-slice partials (bit-layout identical to float pairs) ---
        {
            #pragma unroll
            for (int ri = 0; ri < 4; ++ri) {
                float* p = part + ws * 1024 + ((rg << 2) + ri) * 64 + (bg << 3);
                ulonglong2 v0; v0.x = acc2[ri][0]; v0.y = acc2[ri][1];
                ulonglong2 v1; v1.x = acc2[ri][2]; v1.y = acc2[ri][3];
                *reinterpret_cast<ulonglong2*>(p)     = v0;
                *reinterpret_cast<ulonglong2*>(p + 4) = v1;
            }
        }
        __syncthreads();

        // --- reduce 8 partials + bias -> gates ---
        {
            const int row = tid >> 4;
            const int b0 = (tid & 15) << 2;
            ulonglong2 s; s.x = 0ull; s.y = 0ull;
            #pragma unroll
            for (int p = 0; p < 8; ++p) {
                const ulonglong2 v = *reinterpret_cast<const ulonglong2*>(part + p * 1024 + row * 64 + b0);
                fadd2(s.x, v.x);
                fadd2(s.y, v.y);
            }
            const unsigned long long bd = pack_dup(bias_s[row]);
            fadd2(s.x, bd);
            fadd2(s.y, bd);
            *reinterpret_cast<ulonglong2*>(gates + row * 64 + b0) = s;
        }
        __syncthreads();

        // --- cell update: one thread per (unit, batch) ---
        {
            const int ul = tid >> 6;
            const int b = tid & 63;
            const float gi = gates[(0 * 4 + ul) * 64 + b];
            const float gf = gates[(1 * 4 + ul) * 64 + b];
            const float gg = gates[(2 * 4 + ul) * 64 + b];
            const float go = gates[(3 * 4 + ul) * 64 + b];
            const float i_ = 1.0f / (1.0f + expf(-gi));
            const float f_ = 1.0f / (1.0f + expf(-gf));
            const float g_ = tanhf(gg);
            const float o_ = 1.0f / (1.0f + expf(-go));
            const float cn = f_ * c_s[ul * 64 + b] + i_ * g_;
            c_s[ul * 64 + b] = cn;
            const float h = o_ * tanhf(cn);
            const int col = cta * 4 + ul;
            g_hbuf[((t + 1) & 1) * (HH * BB) + col * BB + b] = h;
            if (LAYER == 0)
                g_out0[(size_t)t * (HH * BB) + col * BB + b] = h;
            if (t == TT - 1) {
                d_out[64 + LAYER * (BB * HH) + (size_t)b * HH + col] = h;
                d_out[64 + 2 * (BB * HH) + LAYER * (BB * HH) + (size_t)b * HH + col] = cn;
            }
        }
        grid_barrier(tid, bar_target);
    }
}

// ---------------------------------------------------------------------------
// FC: out[b] = dot(hn1[b,:], fc_w) + fc_b
// ---------------------------------------------------------------------------
__global__ void fc_kernel(const float* __restrict__ fc_w,
                          const float* __restrict__ fc_b,
                          float* __restrict__ d_out) {
    const int b = blockIdx.x;
    const int tid = threadIdx.x;
    const float* h = d_out + 64 + (BB * HH) + (size_t)b * HH;
    float s = 0.0f;
    for (int k = tid; k < HH; k += 128) s += h[k] * fc_w[k];
    #pragma unroll
    for (int off = 16; off > 0; off >>= 1) s += __shfl_down_sync(0xffffffffu, s, off);
    __shared__ float wsum[4];
    if ((tid & 31) == 0) wsum[tid >> 5] = s;
    __syncthreads();
    if (tid == 0) d_out[b] = wsum[0] + wsum[1] + wsum[2] + wsum[3] + fc_b[0];
}

// ---------------------------------------------------------------------------
// Launch
// ---------------------------------------------------------------------------
extern "C" void kernel_launch(void* const* d_in, const int* in_sizes, int n_in,
                              void* d_out, int out_size) {
    const float* x     = (const float*)d_in[0];
    const float* W_ih0 = (const float*)d_in[1];
    const float* W_hh0 = (const float*)d_in[2];
    const float* b_ih0 = (const float*)d_in[3];
    const float* b_hh0 = (const float*)d_in[4];
    const float* W_ih1 = (const float*)d_in[5];
    const float* W_hh1 = (const float*)d_in[6];
    const float* b_ih1 = (const float*)d_in[7];
    const float* b_hh1 = (const float*)d_in[8];
    const float* fc_w  = (const float*)d_in[9];
    const float* fc_b  = (const float*)d_in[10];
    float* out = (float*)d_out;

    const int smem_tr = 256 * 65 * 4;
    const int smem_l0 = ((256 + HH) * 16 + 2 * 128 * 64 + 8 * 16 * 64 + 16 * 64 + 4 * 64 + 16) * 4;
    const int smem_l1 = ((512 + HH) * 16 + 2 * 128 * 64 + 8 * 16 * 64 + 16 * 64 + 4 * 64 + 16) * 4;

    cudaFuncSetAttribute(transpose_x_kernel,
                         cudaFuncAttributeMaxDynamicSharedMemorySize, smem_tr);
    cudaFuncSetAttribute(lstm_layer_kernel<256, 0>,
                         cudaFuncAttributeMaxDynamicSharedMemorySize, smem_l0);
    cudaFuncSetAttribute(lstm_layer_kernel<512, 1>,
                         cudaFuncAttributeMaxDynamicSharedMemorySize, smem_l1);

    transpose_x_kernel<<<TT, NTH, smem_tr>>>(x);
    lstm_layer_kernel<256, 0><<<NCTA, NTH, smem_l0>>>(W_ih0, W_hh0, b_ih0, b_hh0, out);
    lstm_layer_kernel<512, 1><<<NCTA, NTH, smem_l1>>>(W_ih1, W_hh1, b_ih1, b_hh1, out);
    fc_kernel<<<BB, 128>>>(fc_w, fc_b, out);
}